// round 1
// baseline (speedup 1.0000x reference)
#include <cuda_runtime.h>
#include <math.h>

#define B 8
#define NEV 100000
#define NPARAMS 4000000
#define EPSF 1.1920928955078125e-07f

// Accumulator layout: per level l (W = 32<<l, HW = W*W):
//   32 images (b*4 + fwd*2 + m), each image block = 2*HW floats (num | den)
// LOFF = {0, 65536, 327680, 1376256}, total 5,570,560 floats (22.3 MB)
#define ACCUM_FLOATS 5570560
__device__ float g_accum[ACCUM_FLOATS];
__device__ float g_tref[B][2][2];   // [b][mask][0]=t_first, [1]=t_last
__device__ double g_sums[3];        // 0: event loss, 1: smoothness raw, 2: wd raw

__device__ __constant__ int c_loff[4] = {0, 65536, 327680, 1376256};

// ---------------------------------------------------------------------------
// Zero accumulators + scalar sums
// ---------------------------------------------------------------------------
__global__ void k_zero() {
    int i = blockIdx.x * blockDim.x + threadIdx.x;
    float4* p = reinterpret_cast<float4*>(g_accum);
    if (i < ACCUM_FLOATS / 4) p[i] = make_float4(0.f, 0.f, 0.f, 0.f);
    if (i < 3) g_sums[i] = 0.0;
}

// ---------------------------------------------------------------------------
// Per (batch, mask): t of first masked event (min t) and last masked (max t).
// ts >= 0 so float ordering == int-bit ordering.
// ---------------------------------------------------------------------------
__global__ void k_tref(const float* __restrict__ ts, const int* __restrict__ ps) {
    __shared__ int sfirst[2], slast[2];
    int b = blockIdx.x;
    if (threadIdx.x < 2) { sfirst[threadIdx.x] = 0x7f800000; slast[threadIdx.x] = 0; }
    __syncthreads();
    float tf0 = __int_as_float(0x7f800000), tf1 = tf0;
    float tl0 = 0.f, tl1 = 0.f;
    for (int e = threadIdx.x; e < NEV; e += blockDim.x) {
        float t = ts[b * NEV + e];
        if (ps[b * NEV + e] == 1) { tf0 = fminf(tf0, t); tl0 = fmaxf(tl0, t); }
        else                      { tf1 = fminf(tf1, t); tl1 = fmaxf(tl1, t); }
    }
    atomicMin(&sfirst[0], __float_as_int(tf0));
    atomicMin(&sfirst[1], __float_as_int(tf1));
    atomicMax(&slast[0],  __float_as_int(tl0));
    atomicMax(&slast[1],  __float_as_int(tl1));
    __syncthreads();
    if (threadIdx.x == 0) {
        g_tref[b][0][0] = __int_as_float(sfirst[0]);
        g_tref[b][1][0] = __int_as_float(sfirst[1]);
        g_tref[b][0][1] = __int_as_float(slast[0]);
        g_tref[b][1][1] = __int_as_float(slast[1]);
    }
}

// ---------------------------------------------------------------------------
// Event scatter: for each event, 4 levels x 2 directions, bilinear scatter of
// (weights*t) into num and 1.0 into den.
// ---------------------------------------------------------------------------
__global__ void k_events(const float* __restrict__ f0, const float* __restrict__ f1,
                         const float* __restrict__ f2, const float* __restrict__ f3,
                         const int* __restrict__ xs, const int* __restrict__ ys,
                         const float* __restrict__ ts, const int* __restrict__ ps) {
    int idx = blockIdx.x * blockDim.x + threadIdx.x;
    if (idx >= B * NEV) return;
    int b = idx / NEV;
    int x = xs[idx], y = ys[idx];
    float t = ts[idx];
    int m = (ps[idx] == 1) ? 0 : 1;
    float tfw = g_tref[b][m][1] - t + EPSF;   // forward
    float tbw = g_tref[b][m][0] - t - EPSF;   // backward
    const float* fl[4] = {f0, f1, f2, f3};

#pragma unroll
    for (int l = 0; l < 4; l++) {
        const int W = 32 << l;
        const int HW = W * W;
        const int sh = 3 - l;
        int xl = x >> sh, yl = y >> sh;
        const float* fp = fl[l] + (size_t)b * 2 * HW + yl * W + xl;
        float fx = __ldg(fp);
        float fy = __ldg(fp + HW);
#pragma unroll
        for (int fwd = 0; fwd < 2; fwd++) {
            float t_ = fwd ? tfw : tbw;
            float xf = fminf(fmaxf((float)xl + t_ * fx, 0.f), (float)(W - 1));
            float yf = fminf(fmaxf((float)yl + t_ * fy, 0.f), (float)(W - 1));
            float x0 = floorf(xf), y0 = floorf(yf);
            float x0w = xf - x0, y0w = yf - y0;
            float x1w = 1.f - x0w, y1w = 1.f - y0w;
            int x0i = (int)x0, y0i = (int)y0;
            int x1i = min(x0i + 1, W - 1);
            int y1i = min(y0i + 1, W - 1);
            float* num = g_accum + c_loff[l] + (size_t)(((b * 2 + fwd) * 2 + m)) * 2 * HW;
            float* den = num + HW;
            int Ia = x1i + y1i * W;
            int Ib = x0i + y1i * W;
            int Ic = x1i + y0i * W;
            int Id = x0i + y0i * W;
            atomicAdd(num + Ia, x0w * y0w * t);
            atomicAdd(num + Ib, x1w * y0w * t);
            atomicAdd(num + Ic, x0w * y1w * t);
            atomicAdd(num + Id, x1w * y1w * t);
            atomicAdd(den + Ia, 1.f);
            atomicAdd(den + Ib, 1.f);
            atomicAdd(den + Ic, 1.f);
            atomicAdd(den + Id, 1.f);
        }
    }
}

// ---------------------------------------------------------------------------
// Block reduce helper: float per-thread -> one double atomicAdd per block.
// ---------------------------------------------------------------------------
__device__ __forceinline__ void block_reduce_add(float acc, double* target) {
    __shared__ double swarp[32];
    for (int o = 16; o > 0; o >>= 1) acc += __shfl_down_sync(0xffffffffu, acc, o);
    int wid = threadIdx.x >> 5, lid = threadIdx.x & 31;
    if (lid == 0) swarp[wid] = (double)acc;
    __syncthreads();
    if (threadIdx.x == 0) {
        int nw = (blockDim.x + 31) >> 5;
        double s = 0.0;
        for (int w = 0; w < nw; w++) s += swarp[w];
        atomicAdd(target, s);
    }
}

// ---------------------------------------------------------------------------
// Event-loss reduction: sum over all 2,785,280 pixels of sqrt(r^2 + 1e-6).
// ---------------------------------------------------------------------------
__global__ void k_evreduce() {
    const int TOTAL = 2785280;
    int stride = gridDim.x * blockDim.x;
    float acc = 0.f;
    for (int i = blockIdx.x * blockDim.x + threadIdx.x; i < TOTAL; i += stride) {
        int l, rem;
        if (i < 32768)       { l = 0; rem = i; }
        else if (i < 163840) { l = 1; rem = i - 32768; }
        else if (i < 688128) { l = 2; rem = i - 163840; }
        else                 { l = 3; rem = i - 688128; }
        int lg = 10 + 2 * l;          // log2(HW)
        int HW = 1 << lg;
        int img = rem >> lg;
        int pix = rem & (HW - 1);
        int base = c_loff[l] + img * 2 * HW;
        float num = g_accum[base + pix];
        float den = g_accum[base + HW + pix];
        float r = num / (den + EPSF);
        acc += sqrtf(r * r + 1e-6f);
    }
    block_reduce_add(acc, &g_sums[0]);
}

// ---------------------------------------------------------------------------
// Smoothness: per level, 4 Charbonnier means with per-term divisors.
// Raw sum accumulated; final scale of 6.25 applied at combine.
// ---------------------------------------------------------------------------
__global__ void k_smooth(const float* __restrict__ f0, const float* __restrict__ f1,
                         const float* __restrict__ f2, const float* __restrict__ f3) {
    int l = blockIdx.y;
    const float* fl[4] = {f0, f1, f2, f3};
    const float* f = fl[l];
    const int W = 32 << l;
    const int HW = W * W;
    const int n = 16 * HW;   // B*2 planes
    float inv_lr = 1.f / (16.f * W * (W - 1));            // == ud divisor
    float inv_d  = 1.f / (16.f * (W - 1) * (W - 1));
    int stride = gridDim.x * blockDim.x;
    float acc = 0.f;
    for (int i = blockIdx.x * blockDim.x + threadIdx.x; i < n; i += stride) {
        int pix = i & (HW - 1);
        int col = pix & (W - 1);
        int row = pix / W;
        float v = f[i];
        bool hr = (col < W - 1), hd = (row < W - 1);
        if (hr) {
            float r = f[i + 1];
            float d1 = r - v;
            acc += __powf(d1 * d1 + 1e-6f, 0.45f) * inv_lr;
            if (hd) {
                float dn = f[i + W];
                float dr = f[i + W + 1];
                float t1 = dr - v;      // diag1
                float t2 = r - dn;      // diag2
                acc += (__powf(t1 * t1 + 1e-6f, 0.45f) +
                        __powf(t2 * t2 + 1e-6f, 0.45f)) * inv_d;
            }
        }
        if (hd) {
            float dn = f[i + W];
            float d2 = dn - v;
            acc += __powf(d2 * d2 + 1e-6f, 0.45f) * inv_lr;
        }
    }
    block_reduce_add(acc, &g_sums[1]);
}

// ---------------------------------------------------------------------------
// Weight decay: raw sum of params^2.
// ---------------------------------------------------------------------------
__global__ void k_wd(const float* __restrict__ p) {
    int stride = gridDim.x * blockDim.x;
    float acc = 0.f;
    for (int i = blockIdx.x * blockDim.x + threadIdx.x; i < NPARAMS; i += stride) {
        float v = p[i];
        acc += v * v;
    }
    block_reduce_add(acc, &g_sums[2]);
}

// ---------------------------------------------------------------------------
// Final combine:
//   event + smoothness_raw * (200 * 0.5/4 / 4 = 6.25) + wd_raw * (1e-4/2)
// ---------------------------------------------------------------------------
__global__ void k_final(float* out) {
    out[0] = (float)(g_sums[0] + 6.25 * g_sums[1] + 5.0e-5 * g_sums[2]);
}

// ---------------------------------------------------------------------------
extern "C" void kernel_launch(void* const* d_in, const int* in_sizes, int n_in,
                              void* d_out, int out_size) {
    const float* f0 = (const float*)d_in[0];
    const float* f1 = (const float*)d_in[1];
    const float* f2 = (const float*)d_in[2];
    const float* f3 = (const float*)d_in[3];
    const int*   xs = (const int*)d_in[4];
    const int*   ys = (const int*)d_in[5];
    const float* ts = (const float*)d_in[6];
    const int*   ps = (const int*)d_in[7];
    const float* params = (const float*)d_in[10];
    float* out = (float*)d_out;

    k_zero<<<(ACCUM_FLOATS / 4 + 255) / 256, 256>>>();
    k_tref<<<B, 256>>>(ts, ps);
    k_smooth<<<dim3(256, 4), 256>>>(f0, f1, f2, f3);
    k_wd<<<592, 256>>>(params);
    k_events<<<(B * NEV + 255) / 256, 256>>>(f0, f1, f2, f3, xs, ys, ts, ps);
    k_evreduce<<<1024, 256>>>();
    k_final<<<1, 1>>>(out);
}

// round 2
// speedup vs baseline: 1.0045x; 1.0045x over previous
#include <cuda_runtime.h>
#include <math.h>

#define B 8
#define NEV 100000
#define NPARAMS 4000000
#define EPSF 1.1920928955078125e-07f

// Accumulator: float2 per pixel (x=num, y=den).
// Level l: W = 32<<l, HW = W*W, 32 images (img = (b*2+fwd)*2 + m).
// float2 offsets: {0, 32768, 163840, 688128}, total 2,785,280 float2 (22.3MB)
#define ACCUM_F2 2785280
__device__ float2 g_accum[ACCUM_F2];
__device__ float g_tref[B][2][2];   // [b][mask][0]=t_first, [1]=t_last
__device__ double g_sums[3];        // 0: event, 1: smoothness raw, 2: wd raw

__device__ __constant__ int c_loff[4] = {0, 32768, 163840, 688128};

// Event kernel block split
#define S_A   5                      // splits per (b,f,m)
#define NB_A  (B * 2 * 2 * S_A)      // 320 smem blocks (levels 0,1)
#define NB_B  1160                   // global-red blocks (levels 2,3)
#define EV_PER_SPLIT (NEV / S_A)     // 20000

// ---------------------------------------------------------------------------
__global__ void k_zero() {
    int i = blockIdx.x * blockDim.x + threadIdx.x;
    float4* p = reinterpret_cast<float4*>(g_accum);
    if (i < ACCUM_F2 / 2) p[i] = make_float4(0.f, 0.f, 0.f, 0.f);
    if (i < 3) g_sums[i] = 0.0;
}

// ---------------------------------------------------------------------------
__global__ void k_tref(const float* __restrict__ ts, const int* __restrict__ ps) {
    __shared__ int sfirst[2], slast[2];
    int b = blockIdx.x;
    if (threadIdx.x < 2) { sfirst[threadIdx.x] = 0x7f800000; slast[threadIdx.x] = 0; }
    __syncthreads();
    float tf0 = __int_as_float(0x7f800000), tf1 = tf0;
    float tl0 = 0.f, tl1 = 0.f;
    for (int e = threadIdx.x; e < NEV; e += blockDim.x) {
        float t = ts[b * NEV + e];
        if (ps[b * NEV + e] == 1) { tf0 = fminf(tf0, t); tl0 = fmaxf(tl0, t); }
        else                      { tf1 = fminf(tf1, t); tl1 = fmaxf(tl1, t); }
    }
    atomicMin(&sfirst[0], __float_as_int(tf0));
    atomicMin(&sfirst[1], __float_as_int(tf1));
    atomicMax(&slast[0],  __float_as_int(tl0));
    atomicMax(&slast[1],  __float_as_int(tl1));
    __syncthreads();
    if (threadIdx.x == 0) {
        g_tref[b][0][0] = __int_as_float(sfirst[0]);
        g_tref[b][1][0] = __int_as_float(sfirst[1]);
        g_tref[b][0][1] = __int_as_float(slast[0]);
        g_tref[b][1][1] = __int_as_float(slast[1]);
    }
}

// ---------------------------------------------------------------------------
// Bilinear scatter helpers
// ---------------------------------------------------------------------------
__device__ __forceinline__ void scatter_smem(float* sf, int base2, int W,
                                             float xl, float yl, float t_,
                                             float fx, float fy, float t) {
    float xf = fminf(fmaxf(xl + t_ * fx, 0.f), (float)(W - 1));
    float yf = fminf(fmaxf(yl + t_ * fy, 0.f), (float)(W - 1));
    float x0 = floorf(xf), y0 = floorf(yf);
    float x0w = xf - x0, y0w = yf - y0;
    float x1w = 1.f - x0w, y1w = 1.f - y0w;
    int x0i = (int)x0, y0i = (int)y0;
    int x1i = min(x0i + 1, W - 1);
    int y1i = min(y0i + 1, W - 1);
    int Ia = x1i + y1i * W, Ib = x0i + y1i * W;
    int Ic = x1i + y0i * W, Id = x0i + y0i * W;
    atomicAdd(sf + ((base2 + Ia) << 1),     x0w * y0w * t);
    atomicAdd(sf + ((base2 + Ia) << 1) + 1, 1.f);
    atomicAdd(sf + ((base2 + Ib) << 1),     x1w * y0w * t);
    atomicAdd(sf + ((base2 + Ib) << 1) + 1, 1.f);
    atomicAdd(sf + ((base2 + Ic) << 1),     x0w * y1w * t);
    atomicAdd(sf + ((base2 + Ic) << 1) + 1, 1.f);
    atomicAdd(sf + ((base2 + Id) << 1),     x1w * y1w * t);
    atomicAdd(sf + ((base2 + Id) << 1) + 1, 1.f);
}

__device__ __forceinline__ void scatter_gmem(float2* img, int W,
                                             float xl, float yl, float t_,
                                             float fx, float fy, float t) {
    float xf = fminf(fmaxf(xl + t_ * fx, 0.f), (float)(W - 1));
    float yf = fminf(fmaxf(yl + t_ * fy, 0.f), (float)(W - 1));
    float x0 = floorf(xf), y0 = floorf(yf);
    float x0w = xf - x0, y0w = yf - y0;
    float x1w = 1.f - x0w, y1w = 1.f - y0w;
    int x0i = (int)x0, y0i = (int)y0;
    int x1i = min(x0i + 1, W - 1);
    int y1i = min(y0i + 1, W - 1);
    atomicAdd(img + (x1i + y1i * W), make_float2(x0w * y0w * t, 1.f));
    atomicAdd(img + (x0i + y1i * W), make_float2(x1w * y0w * t, 1.f));
    atomicAdd(img + (x1i + y0i * W), make_float2(x0w * y1w * t, 1.f));
    atomicAdd(img + (x0i + y0i * W), make_float2(x1w * y1w * t, 1.f));
}

// ---------------------------------------------------------------------------
// Combined event kernel.
// Blocks [0, NB_A): smem-privatized levels 0,1 keyed (b, fwd, mask, split).
// Blocks [NB_A, NB_A+NB_B): grid-stride events, global float2 reds, levels 2,3.
// ---------------------------------------------------------------------------
__global__ void __launch_bounds__(256)
k_events(const float* __restrict__ f0, const float* __restrict__ f1,
         const float* __restrict__ f2, const float* __restrict__ f3,
         const int* __restrict__ xs, const int* __restrict__ ys,
         const float* __restrict__ ts, const int* __restrict__ ps) {
    extern __shared__ float2 sm[];   // 5120 float2: [0,1024) lvl0, [1024,5120) lvl1
    int tid = threadIdx.x;

    if (blockIdx.x < NB_A) {
        int a = blockIdx.x;
        int s = a % S_A;
        int m = (a / S_A) & 1;
        int f = (a / (S_A * 2)) & 1;
        int b = a / (S_A * 4);

        float* sf = (float*)sm;
        for (int i = tid; i < 5120 * 2; i += 256) sf[i] = 0.f;
        __syncthreads();

        float tref = g_tref[b][m][f ? 1 : 0];
        int pwant = m ? -1 : 1;
        int estart = s * EV_PER_SPLIT, eend = estart + EV_PER_SPLIT;
        const float* fp0 = f0 + (size_t)b * 2 * 1024;
        const float* fp1 = f1 + (size_t)b * 2 * 4096;

        for (int e = estart + tid; e < eend; e += 256) {
            int idx = b * NEV + e;
            if (ps[idx] != pwant) continue;
            int x = xs[idx], y = ys[idx];
            float t = ts[idx];
            float t_ = f ? (tref - t + EPSF) : (tref - t - EPSF);
            {   // level 0 (W=32)
                int xl = x >> 3, yl = y >> 3;
                float fx = __ldg(fp0 + yl * 32 + xl);
                float fy = __ldg(fp0 + 1024 + yl * 32 + xl);
                scatter_smem(sf, 0, 32, (float)xl, (float)yl, t_, fx, fy, t);
            }
            {   // level 1 (W=64)
                int xl = x >> 2, yl = y >> 2;
                float fx = __ldg(fp1 + yl * 64 + xl);
                float fy = __ldg(fp1 + 4096 + yl * 64 + xl);
                scatter_smem(sf, 1024, 64, (float)xl, (float)yl, t_, fx, fy, t);
            }
        }
        __syncthreads();

        int img = (b * 2 + f) * 2 + m;
        float2* g0 = g_accum + c_loff[0] + img * 1024;
        float2* g1 = g_accum + c_loff[1] + img * 4096;
        for (int i = tid; i < 1024; i += 256) {
            float2 v = sm[i];
            if (v.x != 0.f || v.y != 0.f) atomicAdd(g0 + i, v);
        }
        for (int i = tid; i < 4096; i += 256) {
            float2 v = sm[1024 + i];
            if (v.x != 0.f || v.y != 0.f) atomicAdd(g1 + i, v);
        }
    } else {
        int bb = blockIdx.x - NB_A;
        for (int idx = bb * 256 + tid; idx < B * NEV; idx += NB_B * 256) {
            int b = idx / NEV;
            int x = xs[idx], y = ys[idx];
            float t = ts[idx];
            int m = (ps[idx] == 1) ? 0 : 1;
            float tfw = g_tref[b][m][1] - t + EPSF;
            float tbw = g_tref[b][m][0] - t - EPSF;
            int imgb = (b * 2) * 2 + m;   // fwd=0 image; fwd=1 adds 2*HW... see below
            {   // level 2 (W=128)
                int xl = x >> 1, yl = y >> 1;
                const float* fp = f2 + (size_t)b * 2 * 16384;
                float fx = __ldg(fp + yl * 128 + xl);
                float fy = __ldg(fp + 16384 + yl * 128 + xl);
                float2* base = g_accum + c_loff[2];
                scatter_gmem(base + (size_t)(imgb + 2) * 16384, 128,
                             (float)xl, (float)yl, tfw, fx, fy, t);
                scatter_gmem(base + (size_t)imgb * 16384, 128,
                             (float)xl, (float)yl, tbw, fx, fy, t);
            }
            {   // level 3 (W=256)
                const float* fp = f3 + (size_t)b * 2 * 65536;
                float fx = __ldg(fp + y * 256 + x);
                float fy = __ldg(fp + 65536 + y * 256 + x);
                float2* base = g_accum + c_loff[3];
                scatter_gmem(base + (size_t)(imgb + 2) * 65536, 256,
                             (float)x, (float)y, tfw, fx, fy, t);
                scatter_gmem(base + (size_t)imgb * 65536, 256,
                             (float)x, (float)y, tbw, fx, fy, t);
            }
        }
    }
}

// ---------------------------------------------------------------------------
__device__ __forceinline__ void block_reduce_add(float acc, double* target) {
    __shared__ double swarp[32];
    for (int o = 16; o > 0; o >>= 1) acc += __shfl_down_sync(0xffffffffu, acc, o);
    int wid = threadIdx.x >> 5, lid = threadIdx.x & 31;
    if (lid == 0) swarp[wid] = (double)acc;
    __syncthreads();
    if (threadIdx.x == 0) {
        int nw = (blockDim.x + 31) >> 5;
        double s = 0.0;
        for (int w = 0; w < nw; w++) s += swarp[w];
        atomicAdd(target, s);
    }
}

// ---------------------------------------------------------------------------
__global__ void k_evreduce() {
    int stride = gridDim.x * blockDim.x;
    float acc = 0.f;
    for (int i = blockIdx.x * blockDim.x + threadIdx.x; i < ACCUM_F2; i += stride) {
        float2 v = g_accum[i];
        float r = v.x / (v.y + EPSF);
        acc += sqrtf(r * r + 1e-6f);
    }
    block_reduce_add(acc, &g_sums[0]);
}

// ---------------------------------------------------------------------------
__global__ void k_smooth(const float* __restrict__ f0, const float* __restrict__ f1,
                         const float* __restrict__ f2, const float* __restrict__ f3) {
    int l = blockIdx.y;
    const float* fl[4] = {f0, f1, f2, f3};
    const float* f = fl[l];
    const int W = 32 << l;
    const int HW = W * W;
    const int n = 16 * HW;
    float inv_lr = 1.f / (16.f * W * (W - 1));
    float inv_d  = 1.f / (16.f * (W - 1) * (W - 1));
    int stride = gridDim.x * blockDim.x;
    float acc = 0.f;
    for (int i = blockIdx.x * blockDim.x + threadIdx.x; i < n; i += stride) {
        int pix = i & (HW - 1);
        int col = pix & (W - 1);
        int row = pix / W;
        float v = f[i];
        bool hr = (col < W - 1), hd = (row < W - 1);
        if (hr) {
            float r = f[i + 1];
            float d1 = r - v;
            acc += __powf(d1 * d1 + 1e-6f, 0.45f) * inv_lr;
            if (hd) {
                float dn = f[i + W];
                float dr = f[i + W + 1];
                float t1 = dr - v;
                float t2 = r - dn;
                acc += (__powf(t1 * t1 + 1e-6f, 0.45f) +
                        __powf(t2 * t2 + 1e-6f, 0.45f)) * inv_d;
            }
        }
        if (hd) {
            float dn = f[i + W];
            float d2 = dn - v;
            acc += __powf(d2 * d2 + 1e-6f, 0.45f) * inv_lr;
        }
    }
    block_reduce_add(acc, &g_sums[1]);
}

// ---------------------------------------------------------------------------
__global__ void k_wd(const float* __restrict__ p) {
    const float4* p4 = reinterpret_cast<const float4*>(p);
    int stride = gridDim.x * blockDim.x;
    float acc = 0.f;
    for (int i = blockIdx.x * blockDim.x + threadIdx.x; i < NPARAMS / 4; i += stride) {
        float4 v = p4[i];
        acc += v.x * v.x + v.y * v.y + v.z * v.z + v.w * v.w;
    }
    block_reduce_add(acc, &g_sums[2]);
}

// ---------------------------------------------------------------------------
__global__ void k_final(float* out) {
    out[0] = (float)(g_sums[0] + 6.25 * g_sums[1] + 5.0e-5 * g_sums[2]);
}

// ---------------------------------------------------------------------------
extern "C" void kernel_launch(void* const* d_in, const int* in_sizes, int n_in,
                              void* d_out, int out_size) {
    const float* f0 = (const float*)d_in[0];
    const float* f1 = (const float*)d_in[1];
    const float* f2 = (const float*)d_in[2];
    const float* f3 = (const float*)d_in[3];
    const int*   xs = (const int*)d_in[4];
    const int*   ys = (const int*)d_in[5];
    const float* ts = (const float*)d_in[6];
    const int*   ps = (const int*)d_in[7];
    const float* params = (const float*)d_in[10];
    float* out = (float*)d_out;

    k_zero<<<(ACCUM_F2 / 2 + 255) / 256, 256>>>();
    k_tref<<<B, 256>>>(ts, ps);
    k_smooth<<<dim3(256, 4), 256>>>(f0, f1, f2, f3);
    k_wd<<<592, 256>>>(params);
    k_events<<<NB_A + NB_B, 256, 5120 * sizeof(float2)>>>(f0, f1, f2, f3, xs, ys, ts, ps);
    k_evreduce<<<1024, 256>>>();
    k_final<<<1, 1>>>(out);
}

// round 3
// speedup vs baseline: 2.0552x; 2.0460x over previous
#include <cuda_runtime.h>
#include <math.h>

#define B 8
#define NEV 100000
#define NPARAMS 4000000
#define EPSF 1.1920928955078125e-07f

// Accumulator: float2 per pixel (x=num, y=den).
// Level l: W=32<<l, HW=W*W, 32 images, img = (b*2+fwd)*2 + m.
#define ACCUM_F2 2785280
__device__ float2 g_accum[ACCUM_F2];
__device__ float g_tref[B][2][2];       // [b][m][0]=first(bwd), [1]=last(fwd)

// Per-block partial sums (always fully rewritten each launch -> no zeroing race)
#define NB_SM 512
#define NB_WD 256
#define NB_ER 1024
__device__ double g_part_sm[NB_SM];
__device__ double g_part_wd[NB_WD];
__device__ double g_part_er[NB_ER];

__device__ __constant__ int c_loff[4] = {0, 32768, 163840, 688128};

// ---------------------------------------------------------------------------
__device__ __forceinline__ double block_reduce(float acc) {
    __shared__ double swarp[8];
    for (int o = 16; o > 0; o >>= 1) acc += __shfl_down_sync(0xffffffffu, acc, o);
    int wid = threadIdx.x >> 5, lid = threadIdx.x & 31;
    if (lid == 0) swarp[wid] = (double)acc;
    __syncthreads();
    double s = 0.0;
    if (threadIdx.x == 0)
        for (int w = 0; w < 8; w++) s += swarp[w];
    return s;   // valid on thread 0 only
}

// ---------------------------------------------------------------------------
// k_pre: [0,PRE_ZERO) zero accum | [.., +PRE_WD) weight decay | last 4: tref
// ---------------------------------------------------------------------------
#define PRE_ZERO 512
#define PRE_WD   NB_WD
#define PRE_TREF 4
__global__ void __launch_bounds__(256)
k_pre(const float* __restrict__ ts, const int* __restrict__ ps,
      const float* __restrict__ params) {
    int bid = blockIdx.x, tid = threadIdx.x;
    if (bid < PRE_ZERO) {
        float4* p = (float4*)g_accum;
        const int n = ACCUM_F2 / 2;
        for (int i = bid * 256 + tid; i < n; i += PRE_ZERO * 256)
            p[i] = make_float4(0.f, 0.f, 0.f, 0.f);
    } else if (bid < PRE_ZERO + PRE_WD) {
        const float4* p4 = (const float4*)params;
        float acc = 0.f;
        for (int i = (bid - PRE_ZERO) * 256 + tid; i < NPARAMS / 4; i += PRE_WD * 256) {
            float4 v = p4[i];
            acc += v.x * v.x + v.y * v.y + v.z * v.z + v.w * v.w;
        }
        double s = block_reduce(acc);
        if (tid == 0) g_part_wd[bid - PRE_ZERO] = s;
    } else {
        // tref: ts sorted ascending per batch -> first/last matching index scan
        int w = (bid - (PRE_ZERO + PRE_WD)) * 8 + (tid >> 5);  // 0..31
        int lane = tid & 31;
        int b = w >> 2, m = (w >> 1) & 1, which = w & 1;
        int want = m ? -1 : 1;
        const int* pp = ps + b * NEV;
        const float* tt = ts + b * NEV;
        if (which == 0) {       // first matching (backward t_ref)
            bool found = false;
            for (int base = 0; base < NEV && !found; base += 32) {
                int idx = base + lane;
                bool hit = (idx < NEV) && (pp[idx] == want);
                unsigned bal = __ballot_sync(0xffffffffu, hit);
                if (bal) {
                    if (lane == 0) g_tref[b][m][0] = tt[base + __ffs(bal) - 1];
                    found = true;
                }
            }
            if (!found && lane == 0) g_tref[b][m][0] = tt[0];
        } else {                // last matching (forward t_ref)
            bool found = false;
            for (int base = NEV - 1; base >= 0 && !found; base -= 32) {
                int idx = base - lane;
                bool hit = (idx >= 0) && (pp[idx] == want);
                unsigned bal = __ballot_sync(0xffffffffu, hit);
                if (bal) {
                    if (lane == 0) g_tref[b][m][1] = tt[base - (__ffs(bal) - 1)];
                    found = true;
                }
            }
            if (!found && lane == 0) g_tref[b][m][1] = tt[NEV - 1];
        }
    }
}

// ---------------------------------------------------------------------------
__device__ __forceinline__ void scatter(float2* __restrict__ img, int W,
                                        float xl, float yl, float t_,
                                        float fx, float fy, float t) {
    float xf = fminf(fmaxf(fmaf(t_, fx, xl), 0.f), (float)(W - 1));
    float yf = fminf(fmaxf(fmaf(t_, fy, yl), 0.f), (float)(W - 1));
    float x0 = floorf(xf), y0 = floorf(yf);
    float x0w = xf - x0, y0w = yf - y0;
    float x1w = 1.f - x0w, y1w = 1.f - y0w;
    int x0i = (int)x0, y0i = (int)y0;
    int x1i = min(x0i + 1, W - 1);
    int y1i = min(y0i + 1, W - 1);
    atomicAdd(img + (x1i + y1i * W), make_float2(x0w * y0w * t, 1.f));
    atomicAdd(img + (x0i + y1i * W), make_float2(x1w * y0w * t, 1.f));
    atomicAdd(img + (x1i + y0i * W), make_float2(x0w * y1w * t, 1.f));
    atomicAdd(img + (x0i + y0i * W), make_float2(x1w * y1w * t, 1.f));
}

// ---------------------------------------------------------------------------
// k_main: blocks [0,NB_SM): smoothness (MUFU pipe). [NB_SM, ..): events (LSU).
// ---------------------------------------------------------------------------
#define NB_EV 3125           // 800000 / 256
__device__ __constant__ int c_smb[5] = {0, 384, 480, 504, 512}; // l3,l2,l1,l0 ranges

__global__ void __launch_bounds__(256)
k_main(const float* __restrict__ f0, const float* __restrict__ f1,
       const float* __restrict__ f2, const float* __restrict__ f3,
       const int* __restrict__ xs, const int* __restrict__ ys,
       const float* __restrict__ ts, const int* __restrict__ ps) {
    int tid = threadIdx.x;
    if (blockIdx.x < NB_SM) {
        // ---- smoothness ----
        int l, b0, b1;
        if (blockIdx.x < c_smb[1])      { l = 3; b0 = c_smb[0]; b1 = c_smb[1]; }
        else if (blockIdx.x < c_smb[2]) { l = 2; b0 = c_smb[1]; b1 = c_smb[2]; }
        else if (blockIdx.x < c_smb[3]) { l = 1; b0 = c_smb[2]; b1 = c_smb[3]; }
        else                            { l = 0; b0 = c_smb[3]; b1 = c_smb[4]; }
        const float* f = (l == 3) ? f3 : (l == 2) ? f2 : (l == 1) ? f1 : f0;
        const int W = 32 << l;
        const int HW = W * W;
        const int n = 16 * HW;
        float inv_lr = 1.f / (16.f * W * (W - 1));
        float inv_d  = 1.f / (16.f * (W - 1) * (W - 1));
        int stride = (b1 - b0) * 256;
        float acc = 0.f;
        for (int i = (blockIdx.x - b0) * 256 + tid; i < n; i += stride) {
            int pix = i & (HW - 1);
            int col = pix & (W - 1);
            int row = pix >> (5 + l);
            float v = f[i];
            bool hr = (col < W - 1), hd = (row < W - 1);
            if (hr) {
                float r = f[i + 1];
                float d1 = r - v;
                acc += __powf(d1 * d1 + 1e-6f, 0.45f) * inv_lr;
                if (hd) {
                    float dn = f[i + W];
                    float dr = f[i + W + 1];
                    float t1 = dr - v;
                    float t2 = r - dn;
                    acc += (__powf(t1 * t1 + 1e-6f, 0.45f) +
                            __powf(t2 * t2 + 1e-6f, 0.45f)) * inv_d;
                }
            }
            if (hd) {
                float dn = f[i + W];
                float d2 = dn - v;
                acc += __powf(d2 * d2 + 1e-6f, 0.45f) * inv_lr;
            }
        }
        double s = block_reduce(acc);
        if (tid == 0) g_part_sm[blockIdx.x] = s;
    } else {
        // ---- events: one event per thread, all 4 levels x 2 dirs ----
        int idx = (blockIdx.x - NB_SM) * 256 + tid;
        if (idx >= B * NEV) return;
        int b = idx / NEV;
        int x = xs[idx], y = ys[idx];
        float t = ts[idx];
        int m = (ps[idx] == 1) ? 0 : 1;
        float tfw = g_tref[b][m][1] - t + EPSF;
        float tbw = g_tref[b][m][0] - t - EPSF;
        const float* fl[4] = {f0, f1, f2, f3};
#pragma unroll
        for (int l = 0; l < 4; l++) {
            const int W = 32 << l;
            const int HW = W * W;
            int xl = x >> (3 - l), yl = y >> (3 - l);
            const float* fp = fl[l] + (size_t)b * 2 * HW + yl * W + xl;
            float fx = __ldg(fp);
            float fy = __ldg(fp + HW);
            float2* base = g_accum + c_loff[l];
            scatter(base + (size_t)((b * 2 + 1) * 2 + m) * HW, W,
                    (float)xl, (float)yl, tfw, fx, fy, t);
            scatter(base + (size_t)((b * 2 + 0) * 2 + m) * HW, W,
                    (float)xl, (float)yl, tbw, fx, fy, t);
        }
    }
}

// ---------------------------------------------------------------------------
__global__ void __launch_bounds__(256) k_evreduce() {
    int stride = NB_ER * 256;
    float acc = 0.f;
    for (int i = blockIdx.x * 256 + threadIdx.x; i < ACCUM_F2; i += stride) {
        float2 v = g_accum[i];
        float r = __fdividef(v.x, v.y + EPSF);
        acc += sqrtf(fmaf(r, r, 1e-6f));
    }
    double s = block_reduce(acc);
    if (threadIdx.x == 0) g_part_er[blockIdx.x] = s;
}

// ---------------------------------------------------------------------------
__global__ void __launch_bounds__(256) k_final(float* out) {
    __shared__ double swarp[8];
    double s = 0.0;
    for (int i = threadIdx.x; i < NB_ER; i += 256) s += g_part_er[i];
    for (int i = threadIdx.x; i < NB_SM; i += 256) s += 6.25 * g_part_sm[i];
    for (int i = threadIdx.x; i < NB_WD; i += 256) s += 5.0e-5 * g_part_wd[i];
    for (int o = 16; o > 0; o >>= 1) s += __shfl_down_sync(0xffffffffu, s, o);
    if ((threadIdx.x & 31) == 0) swarp[threadIdx.x >> 5] = s;
    __syncthreads();
    if (threadIdx.x == 0) {
        double r = 0.0;
        for (int w = 0; w < 8; w++) r += swarp[w];
        out[0] = (float)r;
    }
}

// ---------------------------------------------------------------------------
extern "C" void kernel_launch(void* const* d_in, const int* in_sizes, int n_in,
                              void* d_out, int out_size) {
    const float* f0 = (const float*)d_in[0];
    const float* f1 = (const float*)d_in[1];
    const float* f2 = (const float*)d_in[2];
    const float* f3 = (const float*)d_in[3];
    const int*   xs = (const int*)d_in[4];
    const int*   ys = (const int*)d_in[5];
    const float* ts = (const float*)d_in[6];
    const int*   ps = (const int*)d_in[7];
    const float* params = (const float*)d_in[10];
    float* out = (float*)d_out;

    k_pre<<<PRE_ZERO + PRE_WD + PRE_TREF, 256>>>(ts, ps, params);
    k_main<<<NB_SM + NB_EV, 256>>>(f0, f1, f2, f3, xs, ys, ts, ps);
    k_evreduce<<<NB_ER, 256>>>();
    k_final<<<1, 256>>>(out);
}

// round 4
// speedup vs baseline: 2.6337x; 1.2815x over previous
#include <cuda_runtime.h>
#include <math.h>

#define B 8
#define NEV 100000
#define NPARAMS 4000000
#define EPSF 1.1920928955078125e-07f

// Accumulator: float2 per pixel (x=num, y=den), 16B-aligned for v4 REDs.
#define ACCUM_F2 2785280
__device__ __align__(16) float2 g_accum[ACCUM_F2];
__device__ float g_tref[B][2][2];       // [b][m][0]=first(bwd), [1]=last(fwd)

#define NB_SM 512
#define NB_WD 256
#define NB_ER 1024
__device__ double g_part_sm[NB_SM];
__device__ double g_part_wd[NB_WD];
__device__ double g_part_er[NB_ER];
__device__ unsigned g_done;

__device__ __constant__ int c_loff[4] = {0, 32768, 163840, 688128};

// ---------------------------------------------------------------------------
__device__ __forceinline__ void red4(float2* addr, float a, float b, float c, float d) {
    asm volatile("red.global.add.v4.f32 [%0], {%1,%2,%3,%4};" ::
                 "l"(addr), "f"(a), "f"(b), "f"(c), "f"(d) : "memory");
}
__device__ __forceinline__ void red2(float2* addr, float a, float b) {
    asm volatile("red.global.add.v2.f32 [%0], {%1,%2};" ::
                 "l"(addr), "f"(a), "f"(b) : "memory");
}

// ---------------------------------------------------------------------------
__device__ __forceinline__ double block_reduce(float acc) {
    __shared__ double swarp[8];
    for (int o = 16; o > 0; o >>= 1) acc += __shfl_down_sync(0xffffffffu, acc, o);
    int wid = threadIdx.x >> 5, lid = threadIdx.x & 31;
    if (lid == 0) swarp[wid] = (double)acc;
    __syncthreads();
    double s = 0.0;
    if (threadIdx.x == 0)
        for (int w = 0; w < 8; w++) s += swarp[w];
    return s;
}

// ---------------------------------------------------------------------------
// k_pre: zero accum + counter | weight decay | tref scans
// ---------------------------------------------------------------------------
#define PRE_ZERO 512
#define PRE_WD   NB_WD
#define PRE_TREF 4
__global__ void __launch_bounds__(256)
k_pre(const float* __restrict__ ts, const int* __restrict__ ps,
      const float* __restrict__ params) {
    int bid = blockIdx.x, tid = threadIdx.x;
    if (bid < PRE_ZERO) {
        if (bid == 0 && tid == 0) g_done = 0;
        float4* p = (float4*)g_accum;
        const int n = ACCUM_F2 / 2;
        for (int i = bid * 256 + tid; i < n; i += PRE_ZERO * 256)
            p[i] = make_float4(0.f, 0.f, 0.f, 0.f);
    } else if (bid < PRE_ZERO + PRE_WD) {
        const float4* p4 = (const float4*)params;
        float acc = 0.f;
        for (int i = (bid - PRE_ZERO) * 256 + tid; i < NPARAMS / 4; i += PRE_WD * 256) {
            float4 v = p4[i];
            acc += v.x * v.x + v.y * v.y + v.z * v.z + v.w * v.w;
        }
        double s = block_reduce(acc);
        if (tid == 0) g_part_wd[bid - PRE_ZERO] = s;
    } else {
        int w = (bid - (PRE_ZERO + PRE_WD)) * 8 + (tid >> 5);  // 0..31
        int lane = tid & 31;
        int b = w >> 2, m = (w >> 1) & 1, which = w & 1;
        int want = m ? -1 : 1;
        const int* pp = ps + b * NEV;
        const float* tt = ts + b * NEV;
        if (which == 0) {       // first matching (backward t_ref)
            bool found = false;
            for (int base = 0; base < NEV && !found; base += 32) {
                int idx = base + lane;
                bool hit = (idx < NEV) && (pp[idx] == want);
                unsigned bal = __ballot_sync(0xffffffffu, hit);
                if (bal) {
                    if (lane == 0) g_tref[b][m][0] = tt[base + __ffs(bal) - 1];
                    found = true;
                }
            }
            if (!found && lane == 0) g_tref[b][m][0] = tt[0];
        } else {                // last matching (forward t_ref)
            bool found = false;
            for (int base = NEV - 1; base >= 0 && !found; base -= 32) {
                int idx = base - lane;
                bool hit = (idx >= 0) && (pp[idx] == want);
                unsigned bal = __ballot_sync(0xffffffffu, hit);
                if (bal) {
                    if (lane == 0) g_tref[b][m][1] = tt[base - (__ffs(bal) - 1)];
                    found = true;
                }
            }
            if (!found && lane == 0) g_tref[b][m][1] = tt[NEV - 1];
        }
    }
}

// ---------------------------------------------------------------------------
// Bilinear scatter. Corner weights: (x0,*)->x1w, (x1,*)->x0w; rows y0->y1w, y1->y0w.
// Even x0: single v4 RED per row (x1=x0+1 always in-bounds, no clamp possible).
// Odd x0: two v2 REDs per row (handles x-clamp at x0=W-1 naturally).
// ---------------------------------------------------------------------------
__device__ __forceinline__ void scatter(float2* __restrict__ img, int W,
                                        float xl, float yl, float t_,
                                        float fx, float fy, float t) {
    float xf = fminf(fmaxf(fmaf(t_, fx, xl), 0.f), (float)(W - 1));
    float yf = fminf(fmaxf(fmaf(t_, fy, yl), 0.f), (float)(W - 1));
    float x0 = floorf(xf), y0 = floorf(yf);
    float x0w = xf - x0, y0w = yf - y0;
    float x1w = 1.f - x0w, y1w = 1.f - y0w;
    int x0i = (int)x0, y0i = (int)y0;
    int y1i = min(y0i + 1, W - 1);
    float nA = x1w * t;    // x0 column num scale
    float nB = x0w * t;    // x1 column num scale
    if (!(x0i & 1)) {
        float2* r0 = img + (y0i * W + x0i);
        float2* r1 = img + (y1i * W + x0i);
        red4(r0, nA * y1w, 1.f, nB * y1w, 1.f);
        red4(r1, nA * y0w, 1.f, nB * y0w, 1.f);
    } else {
        int x1i = min(x0i + 1, W - 1);
        float2* p00 = img + (y0i * W + x0i);
        float2* p01 = img + (y0i * W + x1i);
        float2* p10 = img + (y1i * W + x0i);
        float2* p11 = img + (y1i * W + x1i);
        red2(p00, nA * y1w, 1.f);
        red2(p01, nB * y1w, 1.f);
        red2(p10, nA * y0w, 1.f);
        red2(p11, nB * y0w, 1.f);
    }
}

// ---------------------------------------------------------------------------
// k_main: blocks [0,NB_SM): smoothness (MUFU). [NB_SM,..): events (LSU/RED).
// ---------------------------------------------------------------------------
#define NB_EV 3125
__device__ __constant__ int c_smb[5] = {0, 384, 480, 504, 512};

__global__ void __launch_bounds__(256)
k_main(const float* __restrict__ f0, const float* __restrict__ f1,
       const float* __restrict__ f2, const float* __restrict__ f3,
       const int* __restrict__ xs, const int* __restrict__ ys,
       const float* __restrict__ ts, const int* __restrict__ ps) {
    int tid = threadIdx.x;
    if (blockIdx.x < NB_SM) {
        int l, b0, b1;
        if (blockIdx.x < c_smb[1])      { l = 3; b0 = c_smb[0]; b1 = c_smb[1]; }
        else if (blockIdx.x < c_smb[2]) { l = 2; b0 = c_smb[1]; b1 = c_smb[2]; }
        else if (blockIdx.x < c_smb[3]) { l = 1; b0 = c_smb[2]; b1 = c_smb[3]; }
        else                            { l = 0; b0 = c_smb[3]; b1 = c_smb[4]; }
        const float* f = (l == 3) ? f3 : (l == 2) ? f2 : (l == 1) ? f1 : f0;
        const int W = 32 << l;
        const int HW = W * W;
        const int n = 16 * HW;
        float inv_lr = 1.f / (16.f * W * (W - 1));
        float inv_d  = 1.f / (16.f * (W - 1) * (W - 1));
        int stride = (b1 - b0) * 256;
        float acc = 0.f;
        for (int i = (blockIdx.x - b0) * 256 + tid; i < n; i += stride) {
            int pix = i & (HW - 1);
            int col = pix & (W - 1);
            int row = pix >> (5 + l);
            float v = f[i];
            bool hr = (col < W - 1), hd = (row < W - 1);
            if (hr) {
                float r = f[i + 1];
                float d1 = r - v;
                acc += __powf(d1 * d1 + 1e-6f, 0.45f) * inv_lr;
                if (hd) {
                    float dn = f[i + W];
                    float dr = f[i + W + 1];
                    float t1 = dr - v;
                    float t2 = r - dn;
                    acc += (__powf(t1 * t1 + 1e-6f, 0.45f) +
                            __powf(t2 * t2 + 1e-6f, 0.45f)) * inv_d;
                }
            }
            if (hd) {
                float dn = f[i + W];
                float d2 = dn - v;
                acc += __powf(d2 * d2 + 1e-6f, 0.45f) * inv_lr;
            }
        }
        double s = block_reduce(acc);
        if (tid == 0) g_part_sm[blockIdx.x] = s;
    } else {
        int idx = (blockIdx.x - NB_SM) * 256 + tid;
        if (idx >= B * NEV) return;
        int b = idx / NEV;
        int x = xs[idx], y = ys[idx];
        float t = ts[idx];
        int m = (ps[idx] == 1) ? 0 : 1;
        float tfw = g_tref[b][m][1] - t + EPSF;
        float tbw = g_tref[b][m][0] - t - EPSF;
        const float* fl[4] = {f0, f1, f2, f3};
#pragma unroll
        for (int l = 0; l < 4; l++) {
            const int W = 32 << l;
            const int HW = W * W;
            int xl = x >> (3 - l), yl = y >> (3 - l);
            const float* fp = fl[l] + (size_t)b * 2 * HW + yl * W + xl;
            float fx = __ldg(fp);
            float fy = __ldg(fp + HW);
            float2* base = g_accum + c_loff[l];
            scatter(base + (size_t)((b * 2 + 1) * 2 + m) * HW, W,
                    (float)xl, (float)yl, tfw, fx, fy, t);
            scatter(base + (size_t)((b * 2 + 0) * 2 + m) * HW, W,
                    (float)xl, (float)yl, tbw, fx, fy, t);
        }
    }
}

// ---------------------------------------------------------------------------
// k_evreduce: per-pixel sqrt((num/den)^2 + 1e-6); last block sums all partials.
// ---------------------------------------------------------------------------
__global__ void __launch_bounds__(256) k_evreduce(float* __restrict__ out) {
    const float4* acc4 = (const float4*)g_accum;
    const int n4 = ACCUM_F2 / 2;
    int stride = NB_ER * 256;
    float acc = 0.f;
    for (int i = blockIdx.x * 256 + threadIdx.x; i < n4; i += stride) {
        float4 v = acc4[i];
        float r0 = v.x * __frcp_rn(v.y + EPSF);
        float r1 = v.z * __frcp_rn(v.w + EPSF);
        float q0 = fmaf(r0, r0, 1e-6f);
        float q1 = fmaf(r1, r1, 1e-6f);
        acc += q0 * __frsqrt_rn(q0) + q1 * __frsqrt_rn(q1);
    }
    double s = block_reduce(acc);
    __shared__ bool is_last;
    if (threadIdx.x == 0) {
        g_part_er[blockIdx.x] = s;
        __threadfence();
        unsigned r = atomicAdd(&g_done, 1u);
        is_last = (r == NB_ER - 1);
    }
    __syncthreads();
    if (is_last) {
        __shared__ double swarp[8];
        double tot = 0.0;
        for (int i = threadIdx.x; i < NB_ER; i += 256) tot += g_part_er[i];
        for (int i = threadIdx.x; i < NB_SM; i += 256) tot += 6.25 * g_part_sm[i];
        for (int i = threadIdx.x; i < NB_WD; i += 256) tot += 5.0e-5 * g_part_wd[i];
        for (int o = 16; o > 0; o >>= 1) tot += __shfl_down_sync(0xffffffffu, tot, o);
        if ((threadIdx.x & 31) == 0) swarp[threadIdx.x >> 5] = tot;
        __syncthreads();
        if (threadIdx.x == 0) {
            double r = 0.0;
            for (int w = 0; w < 8; w++) r += swarp[w];
            out[0] = (float)r;
        }
    }
}

// ---------------------------------------------------------------------------
extern "C" void kernel_launch(void* const* d_in, const int* in_sizes, int n_in,
                              void* d_out, int out_size) {
    const float* f0 = (const float*)d_in[0];
    const float* f1 = (const float*)d_in[1];
    const float* f2 = (const float*)d_in[2];
    const float* f3 = (const float*)d_in[3];
    const int*   xs = (const int*)d_in[4];
    const int*   ys = (const int*)d_in[5];
    const float* ts = (const float*)d_in[6];
    const int*   ps = (const int*)d_in[7];
    const float* params = (const float*)d_in[10];
    float* out = (float*)d_out;

    k_pre<<<PRE_ZERO + PRE_WD + PRE_TREF, 256>>>(ts, ps, params);
    k_main<<<NB_SM + NB_EV, 256>>>(f0, f1, f2, f3, xs, ys, ts, ps);
    k_evreduce<<<NB_ER, 256>>>(out);
}